// round 8
// baseline (speedup 1.0000x reference)
#include <cuda_runtime.h>
#include <cuda_fp16.h>
#include <cstdint>

#define MM 16
#define KK 8192
#define NN 8192
#define KCH 8             // split-K chunks
#define KC 1024           // k per chunk (8 groups of 128)
#define RW 520            // smem x row stride in WORDS (== 8 mod 32 -> LDS.64 conflict-free)

// fp32 partials: [KCH][M][N]
__device__ float g_partial[KCH * MM * NN];
// per-n-slice completion counters (64 slices of n128); zero-init, self-resetting
__device__ int g_cnt[64];

__device__ __forceinline__ void mma16816(float c[4],
                                         unsigned a0, unsigned a1, unsigned a2, unsigned a3,
                                         unsigned b0, unsigned b1) {
    asm volatile(
        "mma.sync.aligned.m16n8k16.row.col.f32.f16.f16.f32 "
        "{%0,%1,%2,%3}, {%4,%5,%6,%7}, {%8,%9}, {%0,%1,%2,%3};\n"
        : "+f"(c[0]), "+f"(c[1]), "+f"(c[2]), "+f"(c[3])
        : "r"(a0), "r"(a1), "r"(a2), "r"(a3), "r"(b0), "r"(b1));
}

// Nibbles t and t+4 of w -> exact fp16x2 (q-8, q'-8). Single shift+mask: no aliasing.
__device__ __forceinline__ unsigned dqx(unsigned w, unsigned sh4) {
    unsigned v = ((w >> sh4) & 0x000F000Fu) | 0x64006400u;   // (1024+q, 1024+q')
    __half2 hv = *reinterpret_cast<__half2*>(&v);
    __half2 r = __hsub2(hv, __float2half2_rn(1032.0f));      // exact
    return *reinterpret_cast<unsigned*>(&r);
}

__global__ __launch_bounds__(128, 4)
void q4_gemm_fused(const float* __restrict__ x,
                   const int* __restrict__ qw,
                   const float* __restrict__ scales,
                   const float* __restrict__ bias,
                   float* __restrict__ out) {
    __shared__ __align__(16) __half xs[MM * RW * 2];   // 16 rows * 520 words = 33280 B
    __shared__ int s_old;

    const int tid = threadIdx.x;
    const int kc = blockIdx.y;
    const int warp = tid >> 5;
    const int lane = tid & 31;
    const int g = lane >> 2;        // 0..7
    const int t = lane & 3;         // 0..3
    const unsigned sh4 = 4u * t;
    const int nb = blockIdx.x;
    const int nbase = nb * 128 + warp * 32;

    // ---- Stage x chunk [16][1024] -> word-interleaved fp16 layout ----
    // Per k16 step kt, 8 words: [b0w0,b1w0,b0w1,b1w1,b0w2,b1w2,b0w3,b1w3],
    // where b0 covers k=kt*16..+7, b1 covers +8..+15, bXwc = (k_c, k_{c+4}).
    for (int it = 0; it < 8; ++it) {
        int idx = it * 128 + tid;          // 1024 tasks: (m, kt)
        int m = idx >> 6;
        int kt = idx & 63;
        const float* xp = x + (size_t)m * KK + kc * KC + kt * 16;
        float4 lo0 = *reinterpret_cast<const float4*>(xp);
        float4 lo1 = *reinterpret_cast<const float4*>(xp + 4);
        float4 hi0 = *reinterpret_cast<const float4*>(xp + 8);
        float4 hi1 = *reinterpret_cast<const float4*>(xp + 12);
        __half2 w0 = __floats2half2_rn(lo0.x, lo1.x);   // (k0,k4)
        __half2 w1 = __floats2half2_rn(hi0.x, hi1.x);   // (k8,k12)
        __half2 w2 = __floats2half2_rn(lo0.y, lo1.y);   // (k1,k5)
        __half2 w3 = __floats2half2_rn(hi0.y, hi1.y);   // (k9,k13)
        __half2 w4 = __floats2half2_rn(lo0.z, lo1.z);   // (k2,k6)
        __half2 w5 = __floats2half2_rn(hi0.z, hi1.z);   // (k10,k14)
        __half2 w6 = __floats2half2_rn(lo0.w, lo1.w);   // (k3,k7)
        __half2 w7 = __floats2half2_rn(hi0.w, hi1.w);   // (k11,k15)
        uint4 p0, p1;
        p0.x = *reinterpret_cast<unsigned*>(&w0);
        p0.y = *reinterpret_cast<unsigned*>(&w1);
        p0.z = *reinterpret_cast<unsigned*>(&w2);
        p0.w = *reinterpret_cast<unsigned*>(&w3);
        p1.x = *reinterpret_cast<unsigned*>(&w4);
        p1.y = *reinterpret_cast<unsigned*>(&w5);
        p1.z = *reinterpret_cast<unsigned*>(&w6);
        p1.w = *reinterpret_cast<unsigned*>(&w7);
        __half* dst = &xs[(size_t)m * RW * 2 + kt * 16];
        *reinterpret_cast<uint4*>(dst)     = p0;
        *reinterpret_cast<uint4*>(dst + 8) = p1;
    }
    __syncthreads();

    // ---- Main loop: warp owns n32 (4 interleaved n8-tiles), k = chunk kc ----
    float cm[4][4];
#pragma unroll
    for (int j = 0; j < 4; ++j)
#pragma unroll
        for (int r = 0; r < 4; ++r) cm[j][r] = 0.f;

    const unsigned* xw = reinterpret_cast<const unsigned*>(xs);
    const int arow0 = g * RW;
    const int arow1 = (g + 8) * RW;

    for (int grp = 0; grp < 8; ++grp) {
        const int gidx = kc * 8 + grp;
        const float4 sv0 = __ldg(reinterpret_cast<const float4*>(
            scales + (size_t)gidx * NN + nbase + 8 * t));
        const float4 sv1 = __ldg(reinterpret_cast<const float4*>(
            scales + (size_t)gidx * NN + nbase + 8 * t + 4));

        float ct[4][4];
#pragma unroll
        for (int j = 0; j < 4; ++j)
#pragma unroll
            for (int r = 0; r < 4; ++r) ct[j][r] = 0.f;

#pragma unroll
        for (int kk8 = 0; kk8 < 8; ++kk8) {
            const int kt = grp * 8 + kk8;
            const int* rp = qw + (size_t)(kc * 128 + 2 * kt) * NN + nbase + 4 * g;
            uint4 q0 = __ldg(reinterpret_cast<const uint4*>(rp));        // row 2kt
            uint4 q1 = __ldg(reinterpret_cast<const uint4*>(rp + NN));   // row 2kt+1

            // A fragments: one LDS.64 per row (conflict-free)
            uint2 pa0 = *reinterpret_cast<const uint2*>(xw + arow0 + kt * 8 + 2 * t);
            uint2 pa1 = *reinterpret_cast<const uint2*>(xw + arow1 + kt * 8 + 2 * t);
            // pa0 = (a0, a2), pa1 = (a1, a3)

            mma16816(ct[0], pa0.x, pa1.x, pa0.y, pa1.y, dqx(q0.x, sh4), dqx(q1.x, sh4));
            mma16816(ct[1], pa0.x, pa1.x, pa0.y, pa1.y, dqx(q0.y, sh4), dqx(q1.y, sh4));
            mma16816(ct[2], pa0.x, pa1.x, pa0.y, pa1.y, dqx(q0.z, sh4), dqx(q1.z, sh4));
            mma16816(ct[3], pa0.x, pa1.x, pa0.y, pa1.y, dqx(q0.w, sh4), dqx(q1.w, sh4));
        }

        const float slo[4] = {sv0.x, sv0.y, sv0.z, sv0.w};
        const float shi[4] = {sv1.x, sv1.y, sv1.z, sv1.w};
#pragma unroll
        for (int j = 0; j < 4; ++j) {
            cm[j][0] += ct[j][0] * slo[j];
            cm[j][1] += ct[j][1] * shi[j];
            cm[j][2] += ct[j][2] * slo[j];
            cm[j][3] += ct[j][3] * shi[j];
        }
    }

    // ---- Store fp32 partials (tile j col c -> global col nbase+4c+j) ----
    {
        float* p = g_partial + (size_t)kc * MM * NN;
        const int col = nbase + 8 * t;
        float4 v00 = make_float4(cm[0][0], cm[1][0], cm[2][0], cm[3][0]);
        float4 v01 = make_float4(cm[0][1], cm[1][1], cm[2][1], cm[3][1]);
        float4 v10 = make_float4(cm[0][2], cm[1][2], cm[2][2], cm[3][2]);
        float4 v11 = make_float4(cm[0][3], cm[1][3], cm[2][3], cm[3][3]);
        *reinterpret_cast<float4*>(p + (size_t)g * NN + col)           = v00;
        *reinterpret_cast<float4*>(p + (size_t)g * NN + col + 4)       = v01;
        *reinterpret_cast<float4*>(p + (size_t)(g + 8) * NN + col)     = v10;
        *reinterpret_cast<float4*>(p + (size_t)(g + 8) * NN + col + 4) = v11;
    }

    // ---- Last-block-done finalization for this n-slice ----
    __threadfence();                 // push this thread's partial stores
    __syncthreads();
    if (tid == 0) s_old = atomicAdd(&g_cnt[nb], 1);
    __syncthreads();
    if (s_old == KCH - 1) {
        __threadfence();             // acquire: other blocks' partials now visible
        // 128 threads finalize 16x128 outputs: thread = (colgrp 0..31, rowgrp 0..3)
        const int cg = tid & 31;
        const int rg = tid >> 5;
        const int n0 = nb * 128 + cg * 4;
        float4 bv = __ldg(reinterpret_cast<const float4*>(bias + n0));
        __half hb0 = __float2half_rn(bv.x);
        __half hb1 = __float2half_rn(bv.y);
        __half hb2 = __float2half_rn(bv.z);
        __half hb3 = __float2half_rn(bv.w);
#pragma unroll
        for (int r = 0; r < 4; ++r) {
            const int row = rg * 4 + r;
            const float* pp = g_partial + (size_t)row * NN + n0;
            float4 s = *reinterpret_cast<const float4*>(pp);
#pragma unroll
            for (int c = 1; c < KCH; ++c) {
                float4 b = *reinterpret_cast<const float4*>(pp + (size_t)c * MM * NN);
                s.x += b.x; s.y += b.y; s.z += b.z; s.w += b.w;
            }
            float4 o;
            o.x = __half2float(__hadd(__float2half_rn(s.x), hb0));
            o.y = __half2float(__hadd(__float2half_rn(s.y), hb1));
            o.z = __half2float(__hadd(__float2half_rn(s.z), hb2));
            o.w = __half2float(__hadd(__float2half_rn(s.w), hb3));
            *reinterpret_cast<float4*>(out + (size_t)row * NN + n0) = o;
        }
        if (tid == 0) g_cnt[nb] = 0;   // self-reset for next launch/replay
    }
}

extern "C" void kernel_launch(void* const* d_in, const int* in_sizes, int n_in,
                              void* d_out, int out_size) {
    // Identify inputs by element count (all distinct).
    const float* x    = nullptr;   // 131072
    const int*   qw   = nullptr;   // 8388608
    const float* sc   = nullptr;   // 524288
    const float* bias = nullptr;   // 8192
    for (int i = 0; i < n_in; ++i) {
        switch (in_sizes[i]) {
            case 131072:  x    = (const float*)d_in[i]; break;
            case 8388608: qw   = (const int*)d_in[i];   break;
            case 524288:  sc   = (const float*)d_in[i]; break;
            case 8192:    bias = (const float*)d_in[i]; break;
            default: break;
        }
    }
    float* out = (float*)d_out;

    dim3 grid(NN / 128, KCH);          // (64, 8), 128 threads (4 warps, n32 each)
    q4_gemm_fused<<<grid, 128>>>(x, qw, sc, bias, out);
}